// round 16
// baseline (speedup 1.0000x reference)
#include <cuda_runtime.h>
#include <cuda_bf16.h>
#include <cstdint>

// Problem constants (fixed shapes from reference setup_inputs)
#define BB      4
#define NP      2048
#define NN      8192
#define CC      64
#define NS      32
#define CH      67                     // 3 xyz + 64 features
#define NFSZ    (BB*CH*NP*NS)          // 17563648 floats (new_features)
#define MASKSZ  (BB*NP*NS)             // 262144 (idx_mask)
#define GRES    10                     // cells per axis (cell size 0.1 == RADIUS)
#define NCELL   (GRES*GRES*GRES)       // 1000
#define HCAP    128                    // per-query hit-list capacity (lambda~31)

// ---------------- device scratch (static, allocation-free) ----------------
__device__ __align__(16) float g_featT[(size_t)BB*NN*CC]; // (B,N,C) transposed
__device__ int    g_mask_kind;               // 0=bool8, 1=int32, 2=float32
__device__ int    g_cellStart[BB*(NCELL+1)]; // support CSR starts per batch
__device__ float4 g_csr[BB*NN];              // (x,y,z,idx_bits) sorted by cell
__device__ int    g_qperm[BB*NP];            // queries sorted by cell per batch

__device__ __forceinline__ bool read_mask(const void* p, int i, int kind) {
    if (kind == 2) return ((const float*)p)[i] != 0.0f;
    if (kind == 1) return ((const int*)p)[i] != 0;
    return ((const unsigned char*)p)[i] != 0;
}

__device__ __forceinline__ int cell_of(float x, float y, float z) {
    int cx = min(GRES-1, max(0, (int)(x * (float)GRES)));
    int cy = min(GRES-1, max(0, (int)(y * (float)GRES)));
    int cz = min(GRES-1, max(0, (int)(z * (float)GRES)));
    return (cz*GRES + cy)*GRES + cx;
}

// Block-wide exclusive scan of one value/thread, 1024 threads, 2 barriers.
__device__ __forceinline__ int block_excl_scan(int v, int tid, int* wsum) {
    int lane = tid & 31, wid = tid >> 5;
    int inc = v;
    #pragma unroll
    for (int off = 1; off < 32; off <<= 1) {
        int t = __shfl_up_sync(0xffffffffu, inc, off);
        if (lane >= off) inc += t;
    }
    if (lane == 31) wsum[wid] = inc;
    __syncthreads();
    if (wid == 0) {
        int s = wsum[lane];
        #pragma unroll
        for (int off = 1; off < 32; off <<= 1) {
            int t = __shfl_up_sync(0xffffffffu, s, off);
            if (lane >= off) s += t;
        }
        wsum[lane] = s;
    }
    __syncthreads();
    int add = wid ? wsum[wid - 1] : 0;
    return inc + add - v;     // exclusive
}

// ============ kernel 1: mask-detect + grid build + query sort + transpose ====
// (proven R12/R14 structure)
__global__ void __launch_bounds__(1024) k_prep(const float* __restrict__ sxyz,
                                               const void* __restrict__ smaskp,
                                               const float* __restrict__ qxyz,
                                               const float* __restrict__ feats) {
    __shared__ int   h[1024];
    __shared__ int   wsum[32];
    __shared__ float tile[4][32][33];
    __shared__ int   sh_f, sh_b;

    const int tid = threadIdx.x;

    if (blockIdx.x < BB) {
        // ================= support CSR build for batch b =================
        const int b = blockIdx.x;
        if (tid == 0) { sh_f = 0; sh_b = 0; }
        h[tid] = 0;
        __syncthreads();
        const unsigned* mw = (const unsigned*)smaskp;
        int isf = 0, hib = 0;
        #pragma unroll
        for (int i = 0; i < 8; ++i) {
            unsigned w = mw[tid + i*1024];
            if (w == 0x3F800000u) isf = 1;
            else if (w & 0xFFFFFF00u) hib = 1;
        }
        if (isf) atomicOr(&sh_f, 1);
        if (hib) atomicOr(&sh_b, 1);
        __syncthreads();
        const int kind = sh_f ? 2 : (sh_b ? 0 : 1);
        if (b == 0 && tid == 0) g_mask_kind = kind;

        // load 8 pts/thread; histogram atomic returns within-cell rank
        float px[8], py[8], pz[8];
        int   pc[8], pr[8];
        unsigned pm = 0;
        #pragma unroll
        for (int i = 0; i < 8; ++i) {
            int j = tid + i*1024;
            bool m = read_mask(smaskp, b*NN + j, kind);
            float x = sxyz[(b*3 + 0)*NN + j];
            float y = sxyz[(b*3 + 1)*NN + j];
            float z = sxyz[(b*3 + 2)*NN + j];
            px[i] = x; py[i] = y; pz[i] = z;
            pc[i] = cell_of(x, y, z);
            if (m) { pm |= 1u << i; pr[i] = atomicAdd(&h[pc[i]], 1); }
        }
        __syncthreads();

        int v = h[tid];
        int excl = block_excl_scan(v, tid, wsum);
        if (tid <= NCELL) g_cellStart[b*(NCELL+1) + tid] = excl;
        h[tid] = excl;
        __syncthreads();

        #pragma unroll
        for (int i = 0; i < 8; ++i) {
            if (pm & (1u << i)) {
                int pos = h[pc[i]] + pr[i];
                g_csr[b*NN + pos] =
                    make_float4(px[i], py[i], pz[i], __int_as_float(tid + i*1024));
            }
        }
    } else if (blockIdx.x < 2*BB) {
        // ================= query binning for batch b =================
        const int b = blockIdx.x - BB;
        h[tid] = 0;
        __syncthreads();
        int qc[2], qr[2];
        #pragma unroll
        for (int i = 0; i < 2; ++i) {
            int j = tid + i*1024;
            float x = qxyz[(b*3 + 0)*NP + j];
            float y = qxyz[(b*3 + 1)*NP + j];
            float z = qxyz[(b*3 + 2)*NP + j];
            qc[i] = cell_of(x, y, z);
            qr[i] = atomicAdd(&h[qc[i]], 1);
        }
        __syncthreads();
        int v = h[tid];
        int excl = block_excl_scan(v, tid, wsum);
        h[tid] = excl;
        __syncthreads();
        #pragma unroll
        for (int i = 0; i < 2; ++i)
            g_qperm[b*NP + h[qc[i]] + qr[i]] = tid + i*1024;
    } else {
        // ================= vectorized transpose: 4 engines x 32c x 32j ======
        int tb   = blockIdx.x - 2*BB;        // 0..511
        int tseg = tid >> 8;                 // engine 0..3
        int t    = tid & 255;
        int tile_id = tb*4 + tseg;           // 0..2047
        int b   = tile_id >> 9;
        int rem = tile_id & 511;
        int c0  = (rem >> 8) << 5;
        int j0  = (rem & 255) << 5;

        {
            int ty = t >> 3, tx = t & 7;
            float4 vv = *(const float4*)&feats[(size_t)(b*CC + c0 + ty)*NN + j0 + tx*4];
            tile[tseg][ty][tx*4 + 0] = vv.x;
            tile[tseg][ty][tx*4 + 1] = vv.y;
            tile[tseg][ty][tx*4 + 2] = vv.z;
            tile[tseg][ty][tx*4 + 3] = vv.w;
        }
        __syncthreads();
        {
            int jrow = t >> 3, cq = t & 7;
            float4 vv;
            vv.x = tile[tseg][cq*4 + 0][jrow];
            vv.y = tile[tseg][cq*4 + 1][jrow];
            vv.z = tile[tseg][cq*4 + 2][jrow];
            vv.w = tile[tseg][cq*4 + 3][jrow];
            *(float4*)&g_featT[(size_t)(b*NN + j0 + jrow)*CC + c0 + cq*4] = vv;
        }
    }
}

// ============ kernel 2: fused ordered ball query + gather + store ============
union QGWarp {
    float4 list[HCAP];                 // 2048 B
    float  tile[NS][33];               // 4224 B
};

// candidate -> CSR address via the per-warp row table
#define ISSUE(RD, SREG, VREG)                                            \
    do {                                                                 \
        int c_ = (RD)*32 + lane;                                         \
        (VREG) = (c_ < total);                                           \
        if (VREG) {                                                      \
            int r_ = 0;                                                  \
            _Pragma("unroll")                                            \
            for (int t_ = 1; t_ < 9; ++t_)                               \
                r_ = (c_ >= rpre_sm[w][t_]) ? t_ : r_;                   \
            int e_ = rbase_sm[w][r_] + (c_ - rpre_sm[w][r_]);            \
            (SREG) = csr[e_];                                            \
        }                                                                \
    } while (0)

__global__ void __launch_bounds__(128, 8) k_qg(const float* __restrict__ qxyz,
                                               const void* __restrict__ qmaskp,
                                               const float* __restrict__ sxyz,
                                               float* __restrict__ dout,
                                               int mask_mode) {
    __shared__ QGWarp u[4];
    __shared__ float4 outl[4][NS];
    __shared__ int    cs_sm[NCELL + 1];
    __shared__ int    rbase_sm[4][9];
    __shared__ int    rpre_sm[4][9];

    const int w    = threadIdx.x >> 5;
    const int lane = threadIdx.x & 31;
    const int gq   = blockIdx.x * 4 + w;     // sorted slot
    const int b    = gq >> 11;               // uniform per block
    const int kind = g_mask_kind;
    const int p    = g_qperm[gq];            // original query id

    for (int i = threadIdx.x; i < NCELL + 1; i += 128)
        cs_sm[i] = g_cellStart[b*(NCELL+1) + i];
    __syncthreads();

    bool qm = read_mask(qmaskp, b*NP + p, kind);
    float qx = qxyz[(b*3 + 0)*NP + p];
    float qy = qxyz[(b*3 + 1)*NP + p];
    float qz = qxyz[(b*3 + 2)*NP + p];
    float qq = __fadd_rn(__fadd_rn(__fmul_rn(qx,qx), __fmul_rn(qy,qy)), __fmul_rn(qz,qz));

    // ---------- ball query: flattened candidate stream, 2-deep pipeline ------
    int cnt = 0;
    if (qm) {
        int cx = min(GRES-1, max(0, (int)(qx * (float)GRES)));
        int cy = min(GRES-1, max(0, (int)(qy * (float)GRES)));
        int cz = min(GRES-1, max(0, (int)(qz * (float)GRES)));
        int cx0 = max(cx-1, 0), cx1 = min(cx+1, GRES-1);
        const float4* csr = &g_csr[b*NN];

        // lanes 0..8 build the row table (same row order as dz-major loops)
        int st = 0, ln = 0;
        if (lane < 9) {
            int dz = lane/3 - 1, dy = lane%3 - 1;
            int cz2 = cz + dz, cy2 = cy + dy;
            if (cz2 >= 0 && cz2 < GRES && cy2 >= 0 && cy2 < GRES) {
                int rowbase = (cz2*GRES + cy2)*GRES;
                st = cs_sm[rowbase + cx0];
                ln = cs_sm[rowbase + cx1 + 1] - st;
            }
        }
        int inc = ln;
        #pragma unroll
        for (int off = 1; off < 16; off <<= 1) {
            int t = __shfl_up_sync(0xffffffffu, inc, off);
            if (lane >= off) inc += t;
        }
        if (lane < 9) { rbase_sm[w][lane] = st; rpre_sm[w][lane] = inc - ln; }
        int total = __shfl_sync(0xffffffffu, inc, 8);
        __syncwarp();

        int nrounds = (total + 31) >> 5;
        float4 sA, sB; bool vA = false, vB = false;
        if (nrounds > 0) ISSUE(0, sA, vA);
        if (nrounds > 1) ISSUE(1, sB, vB);
        for (int rd = 0; rd < nrounds; ++rd) {
            float4 s; bool vv;
            if (rd & 1) { s = sB; vv = vB; if (rd + 2 < nrounds) ISSUE(rd + 2, sB, vB); }
            else        { s = sA; vv = vA; if (rd + 2 < nrounds) ISSUE(rd + 2, sA, vA); }
            bool hit = false;
            if (vv) {
                float ss  = __fadd_rn(__fadd_rn(__fmul_rn(s.x,s.x),
                                __fmul_rn(s.y,s.y)), __fmul_rn(s.z,s.z));
                float dot = __fmaf_rn(qz, s.z,
                                __fmaf_rn(qy, s.y, __fmul_rn(qx, s.x)));
                float d2  = __fsub_rn(__fadd_rn(qq, ss), __fmul_rn(2.0f, dot));
                hit = (d2 <= 0.01f);
            }
            unsigned bal = __ballot_sync(0xffffffffu, hit);
            int pos = cnt + __popc(bal & ((1u << lane) - 1u));
            if (hit && pos < HCAP) u[w].list[pos] = s;
            cnt += __popc(bal);
        }
        cnt = min(cnt, HCAP);
    }
    __syncwarp();

    // ---------- rank-select NS smallest original indices ----------
    for (int base = 0; base < cnt; base += 32) {
        int e = base + lane;
        float4 me;
        int v = 0x7FFFFFFF;
        if (e < cnt) { me = u[w].list[e]; v = __float_as_int(me.w); }
        int rank = 0;
        int j = 0;
        for (; j + 4 <= cnt; j += 4) {
            int a0 = __float_as_int(u[w].list[j+0].w);
            int a1 = __float_as_int(u[w].list[j+1].w);
            int a2 = __float_as_int(u[w].list[j+2].w);
            int a3 = __float_as_int(u[w].list[j+3].w);
            rank += (a0 < v) + (a1 < v) + (a2 < v) + (a3 < v);
        }
        for (; j < cnt; ++j) rank += (__float_as_int(u[w].list[j].w) < v);
        if (e < cnt && rank < NS) outl[w][rank] = me;
    }
    __syncwarp();

    float4 sel;
    if (cnt > 0) sel = (lane < cnt) ? outl[w][lane] : outl[w][0];
    else {
        // reference pads with index 0 when no neighbor found
        sel.x = sxyz[(b*3 + 0)*NN];
        sel.y = sxyz[(b*3 + 1)*NN];
        sel.z = sxyz[(b*3 + 2)*NN];
        sel.w = __int_as_float(0);
    }
    int jk = __float_as_int(sel.w);

    // idx_mask output
    int gi = ((b*NP + p) << 5) + lane;
    if (mask_mode == 1)
        dout[(size_t)NFSZ + gi] = (lane < cnt) ? 1.0f : 0.0f;
    else if (mask_mode == 2)
        ((unsigned char*)dout)[(size_t)NFSZ*4 + gi] = (lane < cnt) ? 1 : 0;

    // ---------- xyz channels (coords carried through selection) ----------
    size_t obase = ((size_t)(b*CH)*NP + p) * NS + lane;
    dout[obase + (size_t)0*NP*NS] = (sel.x - qx) * 10.0f;
    dout[obase + (size_t)1*NP*NS] = (sel.y - qy) * 10.0f;
    dout[obase + (size_t)2*NP*NS] = (sel.z - qz) * 10.0f;

    // ---------- features: two 32-channel passes, vectorized gather ----------
    const float* ft = &g_featT[(size_t)(b*NN)*CC];
    const int r4  = lane >> 3;           // row-in-quad 0..3
    const int seg = lane & 7;            // 16B segment 0..7
    const int m8  = (lane & 7) << 2;     // store-side k base
    const int q4  = lane >> 3;           // store-side channel sub
    #pragma unroll
    for (int pass = 0; pass < 2; ++pass) {
        __syncwarp();
        #pragma unroll
        for (int it = 0; it < 8; ++it) {
            int k2 = it*4 + r4;
            int j  = __shfl_sync(0xffffffffu, jk, k2);
            float4 vv = *(const float4*)&ft[(size_t)j*CC + pass*32 + seg*4];
            u[w].tile[k2][seg*4 + 0] = vv.x;
            u[w].tile[k2][seg*4 + 1] = vv.y;
            u[w].tile[k2][seg*4 + 2] = vv.z;
            u[w].tile[k2][seg*4 + 3] = vv.w;
        }
        __syncwarp();
        size_t fbase = ((size_t)(b*CH + 3 + pass*32 + q4)*NP + p) * NS + m8;
        #pragma unroll
        for (int cg = 0; cg < 8; ++cg) {
            float4 vv;
            vv.x = u[w].tile[m8 + 0][cg*4 + q4];
            vv.y = u[w].tile[m8 + 1][cg*4 + q4];
            vv.z = u[w].tile[m8 + 2][cg*4 + q4];
            vv.w = u[w].tile[m8 + 3][cg*4 + q4];
            *(float4*)&dout[fbase + (size_t)(cg*4)*NP*NS] = vv;
        }
    }
}

// ---------------- launch ----------------
extern "C" void kernel_launch(void* const* d_in, const int* in_sizes, int n_in,
                              void* d_out, int out_size) {
    const float* qxyz  = (const float*)d_in[0];
    const float* sxyz  = (const float*)d_in[1];
    const void*  qmask = d_in[2];
    const void*  smask = d_in[3];
    const float* feats = (const float*)d_in[4];
    float* dout = (float*)d_out;

    long long rem = (long long)out_size - (long long)NFSZ;
    int mask_mode = (rem >= MASKSZ) ? 1 : ((rem == MASKSZ/4) ? 2 : 0);

    k_prep<<<2*BB + 512, 1024>>>(sxyz, smask, qxyz, feats);
    k_qg<<<(BB*NP)/4, 128>>>(qxyz, qmask, sxyz, dout, mask_mode);
}

// round 17
// speedup vs baseline: 1.1556x; 1.1556x over previous
#include <cuda_runtime.h>
#include <cuda_bf16.h>
#include <cooperative_groups.h>
#include <cstdint>

namespace cg = cooperative_groups;

// Problem constants (fixed shapes from reference setup_inputs)
#define BB      4
#define NP      2048
#define NN      8192
#define CC      64
#define NS      32
#define CH      67                     // 3 xyz + 64 features
#define NFSZ    (BB*CH*NP*NS)          // 17563648 floats (new_features)
#define MASKSZ  (BB*NP*NS)             // 262144 (idx_mask)
#define GRES    10                     // cells per axis (cell size 0.1 == RADIUS)
#define NCELL   (GRES*GRES*GRES)       // 1000
#define HCAP    128                    // per-query hit-list capacity (lambda~31)
#define CLU     8                      // build cluster size (HW co-scheduled)

// ---------------- device scratch (static, allocation-free) ----------------
__device__ __align__(16) float g_featT[(size_t)BB*NN*CC]; // (B,N,C) transposed
__device__ int    g_mask_kind;               // 0=bool8, 1=int32, 2=float32
__device__ int    g_cellStart[BB*(NCELL+1)]; // support CSR starts per batch
__device__ int    g_qstart[BB*NCELL];        // query bin starts per batch
__device__ float4 g_csr[BB*NN];              // (x,y,z,idx_bits) sorted by cell
__device__ int    g_qperm[BB*NP];            // queries sorted by cell per batch
__device__ int    g_cnt[2*BB*NCELL];         // histograms: support[0..3], query[4..7]

__device__ __forceinline__ bool read_mask(const void* p, int i, int kind) {
    if (kind == 2) return ((const float*)p)[i] != 0.0f;
    if (kind == 1) return ((const int*)p)[i] != 0;
    return ((const unsigned char*)p)[i] != 0;
}

__device__ __forceinline__ int cell_of(float x, float y, float z) {
    int cx = min(GRES-1, max(0, (int)(x * (float)GRES)));
    int cy = min(GRES-1, max(0, (int)(y * (float)GRES)));
    int cz = min(GRES-1, max(0, (int)(z * (float)GRES)));
    return (cz*GRES + cy)*GRES + cx;
}

// Block-wide exclusive scan (512 threads, 16 warps), 2 barriers.
__device__ __forceinline__ int block_excl_scan512(int v, int tid, int* wsum) {
    int lane = tid & 31, wid = tid >> 5;
    int inc = v;
    #pragma unroll
    for (int off = 1; off < 32; off <<= 1) {
        int t = __shfl_up_sync(0xffffffffu, inc, off);
        if (lane >= off) inc += t;
    }
    if (lane == 31) wsum[wid] = inc;
    __syncthreads();
    if (wid == 0) {
        int s = (lane < 16) ? wsum[lane] : 0;
        #pragma unroll
        for (int off = 1; off < 32; off <<= 1) {
            int t = __shfl_up_sync(0xffffffffu, s, off);
            if (lane >= off) s += t;
        }
        wsum[lane] = s;
    }
    __syncthreads();
    int add = wid ? wsum[wid - 1] : 0;
    return inc + add - v;     // exclusive
}

// ============ kernel 1: clustered grid build + transpose (one launch) ========
// Blocks [0,32): build. Cluster c (8 CTAs, HW co-scheduled on 8 SMs) builds
//   batch c: zero hist -> sync -> count via global atomics (rank = return
//   value, kept in regs) -> sync -> rank-0/1 CTAs scan -> sync -> scatter
//   with plain stores. Distributes the old single-SM 8192-atomic serial
//   chain across 8 SMs with hardware barriers (no livelock risk).
// Blocks [32,544): vectorized transpose, 2 engines x 2 iters = 4 tiles each.
__global__ void __cluster_dims__(CLU, 1, 1) __launch_bounds__(512)
k_prep(const float* __restrict__ sxyz, const void* __restrict__ smaskp,
       const float* __restrict__ qxyz, const float* __restrict__ feats) {
    __shared__ float tile[2][32][33];
    __shared__ int   wsum[32];
    __shared__ int   shf, shb;

    const int tid = threadIdx.x;
    const int blk = blockIdx.x;

    if (blk < CLU*BB) {
        cg::cluster_group cluster = cg::this_cluster();
        const int b = blk >> 3;          // batch = cluster id
        const int r = blk & 7;           // CTA rank in cluster

        // ---- phase -1: zero this batch's histograms (125 cells/CTA each) ----
        if (tid < 125) {
            g_cnt[b*NCELL      + r*125 + tid] = 0;
            g_cnt[(BB+b)*NCELL + r*125 + tid] = 0;
        }

        // ---- mask dtype detection (CTA-local; 8192 words = full bool8 buf) --
        if (tid == 0) { shf = 0; shb = 0; }
        __syncthreads();
        const unsigned* mw = (const unsigned*)smaskp;
        int isf = 0, hib = 0;
        #pragma unroll
        for (int i = 0; i < 16; ++i) {
            unsigned w = mw[tid + i*512];
            if (w == 0x3F800000u) isf = 1;
            else if (w & 0xFFFFFF00u) hib = 1;
        }
        if (isf) atomicOr(&shf, 1);
        if (hib) atomicOr(&shb, 1);
        __syncthreads();
        const int kind = shf ? 2 : (shb ? 0 : 1);
        if (blk == 0 && tid == 0) g_mask_kind = kind;

        __threadfence();
        cluster.sync();

        // ---- count: 1024 support pts + 256 queries per CTA ----
        float px[2], py[2], pz[2];
        int   pc[2], pr[2];
        bool  pm[2];
        #pragma unroll
        for (int i = 0; i < 2; ++i) {
            int j = r*1024 + i*512 + tid;
            pm[i] = read_mask(smaskp, b*NN + j, kind);
            px[i] = sxyz[(b*3 + 0)*NN + j];
            py[i] = sxyz[(b*3 + 1)*NN + j];
            pz[i] = sxyz[(b*3 + 2)*NN + j];
            pc[i] = cell_of(px[i], py[i], pz[i]);
            if (pm[i]) pr[i] = atomicAdd(&g_cnt[b*NCELL + pc[i]], 1);
        }
        int qc = 0, qr = 0, jq = 0;
        if (tid < 256) {
            jq = r*256 + tid;
            float x = qxyz[(b*3 + 0)*NP + jq];
            float y = qxyz[(b*3 + 1)*NP + jq];
            float z = qxyz[(b*3 + 2)*NP + jq];
            qc = cell_of(x, y, z);
            qr = atomicAdd(&g_cnt[(BB + b)*NCELL + qc], 1);
        }

        __threadfence();
        cluster.sync();

        // ---- scans: rank 0 = support (+sentinel), rank 1 = queries ----
        if (r == 0) {
            int e0 = 2*tid, e1 = 2*tid + 1;
            int v0 = (e0 < NCELL) ? g_cnt[b*NCELL + e0] : 0;
            int v1 = (e1 < NCELL) ? g_cnt[b*NCELL + e1] : 0;
            int ex = block_excl_scan512(v0 + v1, tid, wsum);
            if (e0 < NCELL) g_cellStart[b*(NCELL+1) + e0] = ex;
            if (e1 < NCELL) g_cellStart[b*(NCELL+1) + e1] = ex + v0;
            if (e1 == NCELL-1) g_cellStart[b*(NCELL+1) + NCELL] = ex + v0 + v1;
        } else if (r == 1) {
            int e0 = 2*tid, e1 = 2*tid + 1;
            int v0 = (e0 < NCELL) ? g_cnt[(BB+b)*NCELL + e0] : 0;
            int v1 = (e1 < NCELL) ? g_cnt[(BB+b)*NCELL + e1] : 0;
            int ex = block_excl_scan512(v0 + v1, tid, wsum);
            if (e0 < NCELL) g_qstart[b*NCELL + e0] = ex;
            if (e1 < NCELL) g_qstart[b*NCELL + e1] = ex + v0;
        }

        __threadfence();
        cluster.sync();

        // ---- scatter: plain stores from register state ----
        #pragma unroll
        for (int i = 0; i < 2; ++i) {
            if (pm[i]) {
                int pos = g_cellStart[b*(NCELL+1) + pc[i]] + pr[i];
                int j   = r*1024 + i*512 + tid;
                g_csr[b*NN + pos] =
                    make_float4(px[i], py[i], pz[i], __int_as_float(j));
            }
        }
        if (tid < 256)
            g_qperm[b*NP + g_qstart[b*NCELL + qc] + qr] = jq;
    } else {
        // ---- transpose: 512 blocks x 2 engines x 2 iters = 2048 tiles ----
        const int tb   = blk - CLU*BB;       // 0..511
        const int tseg = tid >> 8;           // engine 0..1
        const int t    = tid & 255;
        const int ty = t >> 3, tx = t & 7;
        #pragma unroll
        for (int it = 0; it < 2; ++it) {
            int tile_id = tb*4 + tseg*2 + it; // 0..2047
            int b   = tile_id >> 9;
            int rem = tile_id & 511;
            int c0  = (rem >> 8) << 5;
            int j0  = (rem & 255) << 5;
            {
                float4 vv = *(const float4*)&feats[(size_t)(b*CC + c0 + ty)*NN + j0 + tx*4];
                tile[tseg][ty][tx*4 + 0] = vv.x;
                tile[tseg][ty][tx*4 + 1] = vv.y;
                tile[tseg][ty][tx*4 + 2] = vv.z;
                tile[tseg][ty][tx*4 + 3] = vv.w;
            }
            __syncthreads();
            {
                int jrow = ty, cq = tx;
                float4 vv;
                vv.x = tile[tseg][cq*4 + 0][jrow];
                vv.y = tile[tseg][cq*4 + 1][jrow];
                vv.z = tile[tseg][cq*4 + 2][jrow];
                vv.w = tile[tseg][cq*4 + 3][jrow];
                *(float4*)&g_featT[(size_t)(b*NN + j0 + jrow)*CC + c0 + cq*4] = vv;
            }
            __syncthreads();
        }
    }
}

// ============ kernel 2: fused ordered ball query + gather + store ============
// (byte-identical to the proven 27.5us version)
union QGWarp {
    float4 list[HCAP];                 // 2048 B
    float  tile[NS][33];               // 4224 B
};

__global__ void __launch_bounds__(128, 9) k_qg(const float* __restrict__ qxyz,
                                               const void* __restrict__ qmaskp,
                                               const float* __restrict__ sxyz,
                                               float* __restrict__ dout,
                                               int mask_mode) {
    __shared__ QGWarp u[4];
    __shared__ float4 outl[4][NS];
    __shared__ int    cs_sm[NCELL + 1];

    const int w    = threadIdx.x >> 5;
    const int lane = threadIdx.x & 31;
    const int gq   = blockIdx.x * 4 + w;     // sorted slot
    const int b    = gq >> 11;               // uniform per block
    const int kind = g_mask_kind;
    const int p    = g_qperm[gq];            // original query id

    for (int i = threadIdx.x; i < NCELL + 1; i += 128)
        cs_sm[i] = g_cellStart[b*(NCELL+1) + i];
    __syncthreads();

    bool qm = read_mask(qmaskp, b*NP + p, kind);
    float qx = qxyz[(b*3 + 0)*NP + p];
    float qy = qxyz[(b*3 + 1)*NP + p];
    float qz = qxyz[(b*3 + 2)*NP + p];
    float qq = __fadd_rn(__fadd_rn(__fmul_rn(qx,qx), __fmul_rn(qy,qy)), __fmul_rn(qz,qz));

    // ---------- ball query ----------
    int cnt = 0;
    if (qm) {
        int cx = min(GRES-1, max(0, (int)(qx * (float)GRES)));
        int cy = min(GRES-1, max(0, (int)(qy * (float)GRES)));
        int cz = min(GRES-1, max(0, (int)(qz * (float)GRES)));
        int cx0 = max(cx-1, 0), cx1 = min(cx+1, GRES-1);
        const float4* csr = &g_csr[b*NN];

        #pragma unroll
        for (int dz = -1; dz <= 1; ++dz) {
            int cz2 = cz + dz;
            if (cz2 < 0 || cz2 >= GRES) continue;
            #pragma unroll
            for (int dy = -1; dy <= 1; ++dy) {
                int cy2 = cy + dy;
                if (cy2 < 0 || cy2 >= GRES) continue;
                int rowbase = (cz2*GRES + cy2)*GRES;
                int start = cs_sm[rowbase + cx0];
                int end   = cs_sm[rowbase + cx1 + 1];
                for (int jj = start; jj < end; jj += 32) {
                    int e = jj + lane;
                    bool hit = false;
                    float4 s;
                    if (e < end) {
                        s = csr[e];
                        float ss  = __fadd_rn(__fadd_rn(__fmul_rn(s.x,s.x),
                                        __fmul_rn(s.y,s.y)), __fmul_rn(s.z,s.z));
                        float dot = __fmaf_rn(qz, s.z,
                                        __fmaf_rn(qy, s.y, __fmul_rn(qx, s.x)));
                        float d2  = __fsub_rn(__fadd_rn(qq, ss), __fmul_rn(2.0f, dot));
                        hit = (d2 <= 0.01f);
                    }
                    unsigned bal = __ballot_sync(0xffffffffu, hit);
                    int pos = cnt + __popc(bal & ((1u << lane) - 1u));
                    if (hit && pos < HCAP) u[w].list[pos] = s;
                    cnt += __popc(bal);
                }
            }
        }
        cnt = min(cnt, HCAP);
    }
    __syncwarp();

    // ---------- rank-select NS smallest original indices ----------
    for (int base = 0; base < cnt; base += 32) {
        int e = base + lane;
        float4 me;
        int v = 0x7FFFFFFF;
        if (e < cnt) { me = u[w].list[e]; v = __float_as_int(me.w); }
        int rank = 0;
        int j = 0;
        for (; j + 4 <= cnt; j += 4) {
            int a0 = __float_as_int(u[w].list[j+0].w);
            int a1 = __float_as_int(u[w].list[j+1].w);
            int a2 = __float_as_int(u[w].list[j+2].w);
            int a3 = __float_as_int(u[w].list[j+3].w);
            rank += (a0 < v) + (a1 < v) + (a2 < v) + (a3 < v);
        }
        for (; j < cnt; ++j) rank += (__float_as_int(u[w].list[j].w) < v);
        if (e < cnt && rank < NS) outl[w][rank] = me;
    }
    __syncwarp();

    float4 sel;
    if (cnt > 0) sel = (lane < cnt) ? outl[w][lane] : outl[w][0];
    else {
        // reference pads with index 0 when no neighbor found
        sel.x = sxyz[(b*3 + 0)*NN];
        sel.y = sxyz[(b*3 + 1)*NN];
        sel.z = sxyz[(b*3 + 2)*NN];
        sel.w = __int_as_float(0);
    }
    int jk = __float_as_int(sel.w);

    // idx_mask output
    int gi = ((b*NP + p) << 5) + lane;
    if (mask_mode == 1)
        dout[(size_t)NFSZ + gi] = (lane < cnt) ? 1.0f : 0.0f;
    else if (mask_mode == 2)
        ((unsigned char*)dout)[(size_t)NFSZ*4 + gi] = (lane < cnt) ? 1 : 0;

    // ---------- xyz channels (coords carried through selection) ----------
    size_t obase = ((size_t)(b*CH)*NP + p) * NS + lane;
    dout[obase + (size_t)0*NP*NS] = (sel.x - qx) * 10.0f;
    dout[obase + (size_t)1*NP*NS] = (sel.y - qy) * 10.0f;
    dout[obase + (size_t)2*NP*NS] = (sel.z - qz) * 10.0f;

    // ---------- features: two 32-channel passes, vectorized gather ----------
    const float* ft = &g_featT[(size_t)(b*NN)*CC];
    const int r4  = lane >> 3;           // row-in-quad 0..3
    const int seg = lane & 7;            // 16B segment 0..7
    const int m8  = (lane & 7) << 2;     // store-side k base
    const int q4  = lane >> 3;           // store-side channel sub
    #pragma unroll
    for (int pass = 0; pass < 2; ++pass) {
        __syncwarp();
        #pragma unroll
        for (int it = 0; it < 8; ++it) {
            int k2 = it*4 + r4;
            int j  = __shfl_sync(0xffffffffu, jk, k2);
            float4 vv = *(const float4*)&ft[(size_t)j*CC + pass*32 + seg*4];
            u[w].tile[k2][seg*4 + 0] = vv.x;
            u[w].tile[k2][seg*4 + 1] = vv.y;
            u[w].tile[k2][seg*4 + 2] = vv.z;
            u[w].tile[k2][seg*4 + 3] = vv.w;
        }
        __syncwarp();
        size_t fbase = ((size_t)(b*CH + 3 + pass*32 + q4)*NP + p) * NS + m8;
        #pragma unroll
        for (int cg2 = 0; cg2 < 8; ++cg2) {
            float4 vv;
            vv.x = u[w].tile[m8 + 0][cg2*4 + q4];
            vv.y = u[w].tile[m8 + 1][cg2*4 + q4];
            vv.z = u[w].tile[m8 + 2][cg2*4 + q4];
            vv.w = u[w].tile[m8 + 3][cg2*4 + q4];
            *(float4*)&dout[fbase + (size_t)(cg2*4)*NP*NS] = vv;
        }
    }
}

// ---------------- launch ----------------
extern "C" void kernel_launch(void* const* d_in, const int* in_sizes, int n_in,
                              void* d_out, int out_size) {
    const float* qxyz  = (const float*)d_in[0];
    const float* sxyz  = (const float*)d_in[1];
    const void*  qmask = d_in[2];
    const void*  smask = d_in[3];
    const float* feats = (const float*)d_in[4];
    float* dout = (float*)d_out;

    long long rem = (long long)out_size - (long long)NFSZ;
    int mask_mode = (rem >= MASKSZ) ? 1 : ((rem == MASKSZ/4) ? 2 : 0);

    k_prep<<<CLU*BB + 512, 512>>>(sxyz, smask, qxyz, feats);  // 544 % 8 == 0
    k_qg<<<(BB*NP)/4, 128>>>(qxyz, qmask, sxyz, dout, mask_mode);
}